// round 16
// baseline (speedup 1.0000x reference)
#include <cuda_runtime.h>
#include <cuda_fp16.h>
#include <math.h>
#include <cstdint>

#define TOK   4096          // B*S
#define SEQ   2048
#define EMB   1024
#define NHEAD 16
#define HDIM  64
#define FFD   4096

// -------- scratch ----
__device__ __half g_h  [TOK * EMB];
__device__ __half g_q  [TOK * EMB];
__device__ __half g_k  [TOK * EMB];
__device__ __half g_v  [TOK * EMB];
__device__ __half g_at [TOK * EMB];
__device__ float  g_x1 [TOK * EMB];
__device__ __half g_h2 [TOK * EMB];
__device__ __half g_ff [TOK * FFD];
// fp16 weights, TRANSPOSED to [N][K]
__device__ __half g_wqT[EMB * EMB];
__device__ __half g_wkT[EMB * EMB];
__device__ __half g_wvT[EMB * EMB];
__device__ __half g_woT[EMB * EMB];
__device__ __half g_w1T[FFD * EMB];
__device__ __half g_w2T[EMB * FFD];

// --------------------------- helpers ------------------------------------------
__device__ __forceinline__ uint32_t smem_u32(const void* p) {
    uint32_t a;
    asm("{ .reg .u64 t; cvta.to.shared.u64 t, %1; cvt.u32.u64 %0, t; }" : "=r"(a) : "l"(p));
    return a;
}
__device__ __forceinline__ uint32_t pack_h2(float lo, float hi) {
    uint32_t r;
    asm("cvt.rn.f16x2.f32 %0, %2, %1;" : "=r"(r) : "f"(lo), "f"(hi));
    return r;
}
__device__ __forceinline__ uint32_t ex2_h2(uint32_t x) {
    uint32_t r;
    asm("ex2.approx.f16x2 %0, %1;" : "=r"(r) : "r"(x));
    return r;
}
__device__ __forceinline__ void cp_async16(uint32_t dst, const void* src) {
    asm volatile("cp.async.cg.shared.global [%0], [%1], 16;" :: "r"(dst), "l"(src));
}
__device__ __forceinline__ void cp_commit() {
    asm volatile("cp.async.commit_group;" ::: "memory");
}
__device__ __forceinline__ void cp_wait0() {
    asm volatile("cp.async.wait_group 0;" ::: "memory");
}
__device__ __forceinline__ void mma_f16(float* d, const uint32_t* a, const uint32_t* b) {
    asm volatile(
        "mma.sync.aligned.m16n8k16.row.col.f32.f16.f16.f32 "
        "{%0,%1,%2,%3},{%4,%5,%6,%7},{%8,%9},{%0,%1,%2,%3};"
        : "+f"(d[0]), "+f"(d[1]), "+f"(d[2]), "+f"(d[3])
        : "r"(a[0]), "r"(a[1]), "r"(a[2]), "r"(a[3]), "r"(b[0]), "r"(b[1]));
}
__device__ __forceinline__ void ldmat4(uint32_t& r0, uint32_t& r1, uint32_t& r2,
                                       uint32_t& r3, uint32_t addr) {
    asm volatile("ldmatrix.sync.aligned.m8n8.x4.shared.b16 {%0,%1,%2,%3}, [%4];"
                 : "=r"(r0), "=r"(r1), "=r"(r2), "=r"(r3) : "r"(addr));
}
__device__ __forceinline__ void ldmat4t(uint32_t& r0, uint32_t& r1, uint32_t& r2,
                                        uint32_t& r3, uint32_t addr) {
    asm volatile("ldmatrix.sync.aligned.m8n8.x4.trans.shared.b16 {%0,%1,%2,%3}, [%4];"
                 : "=r"(r0), "=r"(r1), "=r"(r2), "=r"(r3) : "r"(addr));
}
__device__ __forceinline__ void ldmat2t(uint32_t& r0, uint32_t& r1, uint32_t addr) {
    asm volatile("ldmatrix.sync.aligned.m8n8.x2.trans.shared.b16 {%0,%1}, [%2];"
                 : "=r"(r0), "=r"(r1) : "r"(addr));
}

// ---------- combined weight convert + transpose (all 6 in one launch) ---------
__global__ void cvt_all(const float* __restrict__ wq, const float* __restrict__ wk,
                        const float* __restrict__ wv, const float* __restrict__ wo,
                        const float* __restrict__ w1, const float* __restrict__ w2) {
    const int BE = (EMB / 32) * (EMB / 32);
    const int BF = (FFD / 32) * (EMB / 32);
    int bid = blockIdx.x;
    const float* W; __half* WT; int K, N, lb;
    if (bid < BE)            { W = wq; WT = g_wqT; K = EMB; N = EMB; lb = bid; }
    else if (bid < 2 * BE)   { W = wk; WT = g_wkT; K = EMB; N = EMB; lb = bid - BE; }
    else if (bid < 3 * BE)   { W = wv; WT = g_wvT; K = EMB; N = EMB; lb = bid - 2 * BE; }
    else if (bid < 4 * BE)   { W = wo; WT = g_woT; K = EMB; N = EMB; lb = bid - 3 * BE; }
    else if (bid < 4 * BE + BF) { W = w1; WT = g_w1T; K = EMB; N = FFD; lb = bid - 4 * BE; }
    else                     { W = w2; WT = g_w2T; K = FFD; N = EMB; lb = bid - 4 * BE - BF; }

    int nb = N / 32;
    int n0 = (lb % nb) * 32, k0 = (lb / nb) * 32;

    __shared__ float tile[32][33];
    int tx = threadIdx.x, ty = threadIdx.y;
#pragma unroll
    for (int j = 0; j < 4; j++)
        tile[ty + j * 8][tx] = W[(size_t)(k0 + ty + j * 8) * N + n0 + tx];
    __syncthreads();
#pragma unroll
    for (int j = 0; j < 4; j++)
        WT[(size_t)(n0 + ty + j * 8) * K + k0 + tx] = __float2half(tile[tx][ty + j * 8]);
}

// ------------------------ LayerNorm (vectorized, fp16 out) --------------------
__global__ void ln_kernel(const float* __restrict__ x, const float* __restrict__ g,
                          const float* __restrict__ b, __half* __restrict__ out) {
    int t = blockIdx.x;
    int tid = threadIdx.x;
    int lane = tid & 31, w = tid >> 5;

    float4 v4 = *(const float4*)(x + (size_t)t * EMB + tid * 4);
    float sum = v4.x + v4.y + v4.z + v4.w;
    float sq  = v4.x * v4.x + v4.y * v4.y + v4.z * v4.z + v4.w * v4.w;
#pragma unroll
    for (int o = 16; o > 0; o >>= 1) {
        sum += __shfl_xor_sync(0xffffffffu, sum, o);
        sq  += __shfl_xor_sync(0xffffffffu, sq, o);
    }
    __shared__ float s1[8], s2[8];
    if (lane == 0) { s1[w] = sum; s2[w] = sq; }
    __syncthreads();
    float tot = 0.f, tq = 0.f;
#pragma unroll
    for (int i = 0; i < 8; i++) { tot += s1[i]; tq += s2[i]; }
    float mu   = tot * (1.f / EMB);
    float rstd = rsqrtf(tq * (1.f / EMB) - mu * mu + 1e-5f);

    float4 g4 = *(const float4*)(g + tid * 4);
    float4 b4 = *(const float4*)(b + tid * 4);
    uint32_t h0 = pack_h2((v4.x - mu) * rstd * g4.x + b4.x,
                          (v4.y - mu) * rstd * g4.y + b4.y);
    uint32_t h1 = pack_h2((v4.z - mu) * rstd * g4.z + b4.z,
                          (v4.w - mu) * rstd * g4.w + b4.w);
    *(uint2*)(out + (size_t)t * EMB + tid * 4) = make_uint2(h0, h1);
}

// ------- fp16 mma GEMM, cp.async 4-stage, BK=32, 2 k-tiles per barrier --------
#define ABY   (128 * 80)
#define BBY   (128 * 80)
#define NSTG  4
#define GSM   (NSTG * (ABY + BBY))   // 75776 -> 2 CTA/SM

template <int ACT, int OH>
__device__ __forceinline__
void hgemm_core(const __half* __restrict__ A, const __half* __restrict__ WT,
                const float* __restrict__ bias, const float* __restrict__ res,
                void* __restrict__ Cv, int M, int N, int K, int m0, int n0,
                char* smem) {
    uint32_t sbase = smem_u32(smem);
    int tid  = threadIdx.x;
    int lane = tid & 31, warp = tid >> 5;
    int g = lane >> 2, t = lane & 3;
    int wm = (warp >> 2) * 64;
    int wn = (warp & 3) * 32;

    int lm_r = ((lane >> 3) & 1) * 8 + (lane & 7);
    int lm_k = (lane >> 4) * 8;

    int rrow = tid >> 1;
    int rc   = (tid & 1) * 16;

    const __half* Ap = A  + (size_t)(m0 + rrow) * K + rc;
    const __half* Bp = WT + (size_t)(n0 + rrow) * K + rc;
    uint32_t a_dst0 = sbase + rrow * 80 + rc * 2;
    uint32_t b_dst0 = sbase + NSTG * ABY + rrow * 80 + rc * 2;

    int nkb = K >> 5;     // always even (32 or 128)

#define ISSUEH(kb, s)                                                          \
    do {                                                                       \
        const __half* asrc = Ap + (size_t)(kb) * 32;                           \
        const __half* bsrc = Bp + (size_t)(kb) * 32;                           \
        uint32_t ad = a_dst0 + (s) * ABY;                                      \
        uint32_t bd = b_dst0 + (s) * BBY;                                      \
        cp_async16(ad,      asrc);      cp_async16(ad + 16, asrc + 8);         \
        cp_async16(bd,      bsrc);      cp_async16(bd + 16, bsrc + 8);         \
    } while (0)

#define COMPUTE(kb)                                                            \
    do {                                                                       \
        int buf = (kb) & (NSTG - 1);                                           \
        uint32_t abase = sbase + buf * ABY;                                    \
        uint32_t bbase = sbase + NSTG * ABY + buf * BBY;                       \
        _Pragma("unroll")                                                      \
        for (int ks = 0; ks < 2; ks++) {                                       \
            uint32_t a[4][4], b[4][2];                                         \
            _Pragma("unroll")                                                  \
            for (int mf = 0; mf < 4; mf++) {                                   \
                uint32_t addr = abase +                                        \
                    (uint32_t)((wm + mf * 16 + lm_r) * 80 + (ks * 16 + lm_k) * 2); \
                ldmat4(a[mf][0], a[mf][1], a[mf][2], a[mf][3], addr);          \
            }                                                                  \
            _Pragma("unroll")                                                  \
            for (int pr = 0; pr < 2; pr++) {                                   \
                uint32_t r0, r1, r2, r3;                                       \
                uint32_t addr = bbase +                                        \
                    (uint32_t)((wn + pr * 16 + lm_r) * 80 + (ks * 16 + lm_k) * 2); \
                ldmat4(r0, r1, r2, r3, addr);                                  \
                b[2 * pr][0] = r0; b[2 * pr + 1][0] = r1;                      \
                b[2 * pr][1] = r2; b[2 * pr + 1][1] = r3;                      \
            }                                                                  \
            _Pragma("unroll")                                                  \
            for (int mf = 0; mf < 4; mf++)                                     \
                _Pragma("unroll")                                              \
                for (int nf = 0; nf < 4; nf++)                                 \
                    mma_f16(acc[mf][nf], a[mf], b[nf]);                        \
        }                                                                      \
    } while (0)

    // prologue: tiles 0,1 in one group
    ISSUEH(0, 0);
    ISSUEH(1, 1);
    cp_commit();

    float acc[4][4][4] = {};

    for (int kb = 0; kb < nkb; kb += 2) {
        cp_wait0();          // tiles kb, kb+1 landed
        __syncthreads();     // prior pair's buffers fully consumed by all warps

        if (kb + 3 < nkb) {
            ISSUEH(kb + 2, (kb + 2) & (NSTG - 1));
            ISSUEH(kb + 3, (kb + 3) & (NSTG - 1));
            cp_commit();
        } else if (kb + 2 < nkb) {
            ISSUEH(kb + 2, (kb + 2) & (NSTG - 1));
            cp_commit();
        }

        COMPUTE(kb);
        COMPUTE(kb + 1);
    }
#undef ISSUEH
#undef COMPUTE

#pragma unroll
    for (int mf = 0; mf < 4; mf++) {
#pragma unroll
        for (int nf = 0; nf < 4; nf++) {
            int mA = m0 + wm + mf * 16 + g;
            int mB = mA + 8;
            int n_ = n0 + wn + nf * 8 + 2 * t;
            float bn0 = bias[n_], bn1 = bias[n_ + 1];

            float v00 = acc[mf][nf][0] + bn0;
            float v01 = acc[mf][nf][1] + bn1;
            float v10 = acc[mf][nf][2] + bn0;
            float v11 = acc[mf][nf][3] + bn1;
            if (res) {
                const float2 r0 = *(const float2*)(res + (size_t)mA * N + n_);
                const float2 r1 = *(const float2*)(res + (size_t)mB * N + n_);
                v00 += r0.x; v01 += r0.y; v10 += r1.x; v11 += r1.y;
            }
            if (ACT == 1) {
                v00 = 0.5f * v00 * (1.f + erff(v00 * 0.70710678118654752f));
                v01 = 0.5f * v01 * (1.f + erff(v01 * 0.70710678118654752f));
                v10 = 0.5f * v10 * (1.f + erff(v10 * 0.70710678118654752f));
                v11 = 0.5f * v11 * (1.f + erff(v11 * 0.70710678118654752f));
            }
            if (OH == 1) {
                __half* Ch = (__half*)Cv;
                *(uint32_t*)(Ch + (size_t)mA * N + n_) = pack_h2(v00, v01);
                *(uint32_t*)(Ch + (size_t)mB * N + n_) = pack_h2(v10, v11);
            } else {
                float* Cf = (float*)Cv;
                *(float2*)(Cf + (size_t)mA * N + n_) = make_float2(v00, v01);
                *(float2*)(Cf + (size_t)mB * N + n_) = make_float2(v10, v11);
            }
        }
    }
}

template <int ACT, int OH>
__global__ __launch_bounds__(256, 2)
void h_gemm(const __half* __restrict__ A, const __half* __restrict__ WT,
            const float* __restrict__ bias, const float* __restrict__ res,
            void* __restrict__ C, int M, int N, int K) {
    extern __shared__ char smem[];
    hgemm_core<ACT, OH>(A, WT, bias, res, C, M, N, K,
                        blockIdx.y * 128, blockIdx.x * 128, smem);
}

__global__ __launch_bounds__(256, 2)
void qkv_gemm(const __half* __restrict__ A,
              const float* __restrict__ bq, const float* __restrict__ bk,
              const float* __restrict__ bv,
              __half* __restrict__ Qo, __half* __restrict__ Ko,
              __half* __restrict__ Vo) {
    extern __shared__ char smem[];
    int wsel = blockIdx.x >> 3;
    int n0   = (blockIdx.x & 7) * 128;
    const __half* W;
    const float* bias;
    __half* C;
    if (wsel == 0)      { W = g_wqT; bias = bq; C = Qo; }
    else if (wsel == 1) { W = g_wkT; bias = bk; C = Ko; }
    else                { W = g_wvT; bias = bv; C = Vo; }
    hgemm_core<0, 1>(A, W, bias, nullptr, C, TOK, EMB, EMB,
                     blockIdx.y * 128, n0, smem);
}

// ------ fp16 flash attention (R12 exact: 64-row Q, ex2.f16x2, ones-col) ------
#define HST 72
#define L2E 1.44269504088896340736f

__global__ __launch_bounds__(128)
void attn_h(const __half* __restrict__ Q, const __half* __restrict__ K,
            const __half* __restrict__ V, __half* __restrict__ O) {
    extern __shared__ __half smh[];
    __half* Qs = smh;
    __half* Ks = Qs + 64 * HST;
    __half* Vs = Ks + 64 * HST;
    uint32_t ks_base = smem_u32(Ks);
    uint32_t vs_base = smem_u32(Vs);

    int qt = (int)gridDim.x - 1 - (int)blockIdx.x;
    int bh = blockIdx.y;
    int bb = bh >> 4, hh = bh & 15;
    int tid  = threadIdx.x;
    int warp = tid >> 5, lane = tid & 31;
    int g = lane >> 2, t = lane & 3;
    int r0 = warp * 16;

    size_t base = (size_t)bb * SEQ * EMB + (size_t)hh * HDIM;

    {
        int r = tid >> 1;
        int w = (tid & 1) * 2;
        uint2 val = make_uint2((tid & 1) == 0 ? 0x00003C00u : 0u, 0u);
        *(uint2*)&Vs[r * HST + 64 + w * 2] = val;
    }

    const __half2 sc8 = __float2half2_rn(0.125f);
#pragma unroll
    for (int it = 0; it < 8; it++) {
        int r = (tid >> 4) + it * 8;
        int c = (tid & 15) * 4;
        const __half2* qp = (const __half2*)(Q + base + (size_t)(qt * 64 + r) * EMB + c);
        *(__half2*)&Qs[r * HST + c]     = __hmul2(qp[0], sc8);
        *(__half2*)&Qs[r * HST + c + 2] = __hmul2(qp[1], sc8);
    }
    __syncthreads();

    uint32_t qa[4][4];
#pragma unroll
    for (int kc = 0; kc < 4; kc++) {
        qa[kc][0] = *(const uint32_t*)&Qs[(r0 + g)     * HST + kc * 16 + 2 * t];
        qa[kc][1] = *(const uint32_t*)&Qs[(r0 + g + 8) * HST + kc * 16 + 2 * t];
        qa[kc][2] = *(const uint32_t*)&Qs[(r0 + g)     * HST + kc * 16 + 2 * t + 8];
        qa[kc][3] = *(const uint32_t*)&Qs[(r0 + g + 8) * HST + kc * 16 + 2 * t + 8];
    }

    float o[8][4] = {};
    float oex[4] = {};
    float m0 = -1e30f, m1 = -1e30f;

    int lm_r = ((lane >> 3) & 1) * 8 + (lane & 7);
    int lm_k = (lane >> 4) * 8;

    for (int kt = 0; kt <= qt; kt++) {
#pragma unroll
        for (int it = 0; it < 8; it++) {
            int r = (tid >> 4) + it * 8;
            int c = (tid & 15) * 4;
            size_t go = base + (size_t)(kt * 64 + r) * EMB + c;
            *(uint2*)&Ks[r * HST + c] = *(const uint2*)(K + go);
            *(uint2*)&Vs[r * HST + c] = *(const uint2*)(V + go);
        }
        __syncthreads();

        float s[8][4] = {};
#pragma unroll
        for (int np = 0; np < 4; np++) {
#pragma unroll
            for (int kc = 0; kc < 4; kc++) {
                uint32_t r0v, r1v, r2v, r3v;
                uint32_t addr = ks_base +
                    (uint32_t)(((np * 16 + lm_r) * HST + kc * 16 + lm_k) * 2);
                ldmat4(r0v, r1v, r2v, r3v, addr);
                uint32_t b0[2] = { r0v, r2v };
                uint32_t b1[2] = { r1v, r3v };
                mma_f16(s[2 * np],     qa[kc], b0);
                mma_f16(s[2 * np + 1], qa[kc], b1);
            }
        }

        if (kt == qt) {
            int rowA = r0 + g, rowB = r0 + g + 8;
#pragma unroll
            for (int nf = 0; nf < 8; nf++) {
                int c0 = nf * 8 + 2 * t, c1 = c0 + 1;
                if (c0 > rowA) s[nf][0] = -1e30f;
                if (c1 > rowA) s[nf][1] = -1e30f;
                if (c0 > rowB) s[nf][2] = -1e30f;
                if (c1 > rowB) s[nf][3] = -1e30f;
            }
        }

        float mx0 = -1e30f, mx1 = -1e30f;
#pragma unroll
        for (int nf = 0; nf < 8; nf++) {
            mx0 = fmaxf(mx0, fmaxf(s[nf][0], s[nf][1]));
            mx1 = fmaxf(mx1, fmaxf(s[nf][2], s[nf][3]));
        }
        mx0 = fmaxf(mx0, __shfl_xor_sync(0xffffffffu, mx0, 1));
        mx0 = fmaxf(mx0, __shfl_xor_sync(0xffffffffu, mx0, 2));
        mx1 = fmaxf(mx1, __shfl_xor_sync(0xffffffffu, mx1, 1));
        mx1 = fmaxf(mx1, __shfl_xor_sync(0xffffffffu, mx1, 2));

        float m0n = fmaxf(m0, mx0), m1n = fmaxf(m1, mx1);
        float rs0 = __expf(m0 - m0n), rs1 = __expf(m1 - m1n);
        m0 = m0n; m1 = m1n;
        float mL0 = m0 * L2E, mL1 = m1 * L2E;

        uint32_t pa[4][4];
#pragma unroll
        for (int j = 0; j < 4; j++) {
            pa[j][0] = ex2_h2(pack_h2(fmaf(s[2*j][0],   L2E, -mL0),
                                      fmaf(s[2*j][1],   L2E, -mL0)));
            pa[j][1] = ex2_h2(pack_h2(fmaf(s[2*j][2],   L2E, -mL1),
                                      fmaf(s[2*j][3],   L2E, -mL1)));
            pa[j][2] = ex2_h2(pack_h2(fmaf(s[2*j+1][0], L2E, -mL0),
                                      fmaf(s[2*j+1][1], L2E, -mL0)));
            pa[j][3] = ex2_h2(pack_h2(fmaf(s[2*j+1][2], L2E, -mL1),
                                      fmaf(s[2*j+1][3], L2E, -mL1)));
        }

#pragma unroll
        for (int nf = 0; nf < 8; nf++) {
            o[nf][0] *= rs0; o[nf][1] *= rs0;
            o[nf][2] *= rs1; o[nf][3] *= rs1;
        }
        oex[0] *= rs0; oex[1] *= rs0; oex[2] *= rs1; oex[3] *= rs1;

#pragma unroll
        for (int j = 0; j < 4; j++) {
#pragma unroll
            for (int nfp = 0; nfp < 4; nfp++) {
                uint32_t r0v, r1v, r2v, r3v;
                uint32_t addr = vs_base +
                    (uint32_t)(((j * 16 + lm_r) * HST + nfp * 16 + lm_k) * 2);
                ldmat4t(r0v, r1v, r2v, r3v, addr);
                uint32_t b0[2] = { r0v, r1v };
                uint32_t b1[2] = { r2v, r3v };
                mma_f16(o[2 * nfp],     pa[j], b0);
                mma_f16(o[2 * nfp + 1], pa[j], b1);
            }
            {
                uint32_t e0, e1;
                uint32_t addr = vs_base +
                    (uint32_t)(((j * 16 + (lane & 15)) * HST + 64) * 2);
                ldmat2t(e0, e1, addr);
                uint32_t be[2] = { e0, e1 };
                mma_f16(oex, pa[j], be);
            }
        }
        __syncthreads();
    }

    float lA = __shfl_sync(0xffffffffu, oex[0], lane & ~3);
    float lB = __shfl_sync(0xffffffffu, oex[2], lane & ~3);
    float il0 = 1.f / lA, il1 = 1.f / lB;

    int rowA = qt * 64 + r0 + g;
    int rowB = rowA + 8;
#pragma unroll
    for (int nf = 0; nf < 8; nf++) {
        int c = nf * 8 + 2 * t;
        *(uint32_t*)(O + base + (size_t)rowA * EMB + c) =
            pack_h2(o[nf][0] * il0, o[nf][1] * il0);
        *(uint32_t*)(O + base + (size_t)rowB * EMB + c) =
            pack_h2(o[nf][2] * il1, o[nf][3] * il1);
    }
}

// ------------------------------- launch --------------------------------------
extern "C" void kernel_launch(void* const* d_in, const int* in_sizes, int n_in,
                              void* d_out, int out_size) {
    const float* x     = (const float*)d_in[0];
    const float* ln1_g = (const float*)d_in[2];
    const float* ln1_b = (const float*)d_in[3];
    const float* wq    = (const float*)d_in[4];
    const float* bq    = (const float*)d_in[5];
    const float* wk    = (const float*)d_in[6];
    const float* bk    = (const float*)d_in[7];
    const float* wv    = (const float*)d_in[8];
    const float* bv    = (const float*)d_in[9];
    const float* wo    = (const float*)d_in[10];
    const float* bo    = (const float*)d_in[11];
    const float* ln2_g = (const float*)d_in[12];
    const float* ln2_b = (const float*)d_in[13];
    const float* w1    = (const float*)d_in[14];
    const float* b1    = (const float*)d_in[15];
    const float* w2    = (const float*)d_in[16];
    const float* b2    = (const float*)d_in[17];
    float* out = (float*)d_out;

    __half *h, *q, *k, *v, *at, *h2, *ff;
    float *x1;
    cudaGetSymbolAddress((void**)&h,  g_h);
    cudaGetSymbolAddress((void**)&q,  g_q);
    cudaGetSymbolAddress((void**)&k,  g_k);
    cudaGetSymbolAddress((void**)&v,  g_v);
    cudaGetSymbolAddress((void**)&at, g_at);
    cudaGetSymbolAddress((void**)&x1, g_x1);
    cudaGetSymbolAddress((void**)&h2, g_h2);
    cudaGetSymbolAddress((void**)&ff, g_ff);
    __half *woT, *w1T, *w2T;
    cudaGetSymbolAddress((void**)&woT, g_woT);
    cudaGetSymbolAddress((void**)&w1T, g_w1T);
    cudaGetSymbolAddress((void**)&w2T, g_w2T);

    const int ATTN_SMEM = 3 * 64 * HST * sizeof(__half);   // 27648
    cudaFuncSetAttribute(attn_h, cudaFuncAttributeMaxDynamicSharedMemorySize, ATTN_SMEM);
    cudaFuncSetAttribute(h_gemm<0, 0>, cudaFuncAttributeMaxDynamicSharedMemorySize, GSM);
    cudaFuncSetAttribute(h_gemm<1, 1>, cudaFuncAttributeMaxDynamicSharedMemorySize, GSM);
    cudaFuncSetAttribute(qkv_gemm, cudaFuncAttributeMaxDynamicSharedMemorySize, GSM);

    cvt_all<<<12288, dim3(32, 8)>>>(wq, wk, wv, wo, w1, w2);

    ln_kernel<<<TOK, 256>>>(x, ln1_g, ln1_b, h);

    qkv_gemm<<<dim3(24, TOK / 128), 256, GSM>>>(h, bq, bk, bv, q, k, v);

    attn_h<<<dim3(SEQ / 64, 2 * NHEAD), 128, ATTN_SMEM>>>(q, k, v, at);

    dim3 gE(EMB / 128, TOK / 128);
    h_gemm<0, 0><<<gE, 256, GSM>>>(at, woT, bo, x, x1, TOK, EMB, EMB);

    ln_kernel<<<TOK, 256>>>(x1, ln2_g, ln2_b, h2);

    dim3 gF1(FFD / 128, TOK / 128);
    h_gemm<1, 1><<<gF1, 256, GSM>>>(h2, w1T, b1, nullptr, ff, TOK, FFD, EMB);
    h_gemm<0, 0><<<gE, 256, GSM>>>(ff, w2T, b2, x1, out, TOK, EMB, FFD);
}

// round 17
// speedup vs baseline: 1.1500x; 1.1500x over previous
#include <cuda_runtime.h>
#include <cuda_fp16.h>
#include <math.h>
#include <cstdint>

#define TOK   4096          // B*S
#define SEQ   2048
#define EMB   1024
#define NHEAD 16
#define HDIM  64
#define FFD   4096

// -------- scratch ----
__device__ __half g_h  [TOK * EMB];
__device__ __half g_q  [TOK * EMB];
__device__ __half g_k  [TOK * EMB];
__device__ __half g_v  [TOK * EMB];
__device__ __half g_at [TOK * EMB];
__device__ float  g_x1 [TOK * EMB];
__device__ __half g_h2 [TOK * EMB];
__device__ __half g_ff [TOK * FFD];
// fp16 weights, TRANSPOSED to [N][K]
__device__ __half g_wqT[EMB * EMB];
__device__ __half g_wkT[EMB * EMB];
__device__ __half g_wvT[EMB * EMB];
__device__ __half g_woT[EMB * EMB];
__device__ __half g_w1T[FFD * EMB];
__device__ __half g_w2T[EMB * FFD];

// --------------------------- helpers ------------------------------------------
__device__ __forceinline__ uint32_t smem_u32(const void* p) {
    uint32_t a;
    asm("{ .reg .u64 t; cvta.to.shared.u64 t, %1; cvt.u32.u64 %0, t; }" : "=r"(a) : "l"(p));
    return a;
}
__device__ __forceinline__ uint32_t pack_h2(float lo, float hi) {
    uint32_t r;
    asm("cvt.rn.f16x2.f32 %0, %2, %1;" : "=r"(r) : "f"(lo), "f"(hi));
    return r;
}
__device__ __forceinline__ uint32_t ex2_h2(uint32_t x) {
    uint32_t r;
    asm("ex2.approx.f16x2 %0, %1;" : "=r"(r) : "r"(x));
    return r;
}
__device__ __forceinline__ void cp_async16(uint32_t dst, const void* src) {
    asm volatile("cp.async.cg.shared.global [%0], [%1], 16;" :: "r"(dst), "l"(src));
}
__device__ __forceinline__ void cp_commit() {
    asm volatile("cp.async.commit_group;" ::: "memory");
}
__device__ __forceinline__ void cp_wait2() {
    asm volatile("cp.async.wait_group 2;" ::: "memory");
}
__device__ __forceinline__ void mma_f16(float* d, const uint32_t* a, const uint32_t* b) {
    asm volatile(
        "mma.sync.aligned.m16n8k16.row.col.f32.f16.f16.f32 "
        "{%0,%1,%2,%3},{%4,%5,%6,%7},{%8,%9},{%0,%1,%2,%3};"
        : "+f"(d[0]), "+f"(d[1]), "+f"(d[2]), "+f"(d[3])
        : "r"(a[0]), "r"(a[1]), "r"(a[2]), "r"(a[3]), "r"(b[0]), "r"(b[1]));
}
__device__ __forceinline__ void ldmat4(uint32_t& r0, uint32_t& r1, uint32_t& r2,
                                       uint32_t& r3, uint32_t addr) {
    asm volatile("ldmatrix.sync.aligned.m8n8.x4.shared.b16 {%0,%1,%2,%3}, [%4];"
                 : "=r"(r0), "=r"(r1), "=r"(r2), "=r"(r3) : "r"(addr));
}
__device__ __forceinline__ void ldmat4t(uint32_t& r0, uint32_t& r1, uint32_t& r2,
                                        uint32_t& r3, uint32_t addr) {
    asm volatile("ldmatrix.sync.aligned.m8n8.x4.trans.shared.b16 {%0,%1,%2,%3}, [%4];"
                 : "=r"(r0), "=r"(r1), "=r"(r2), "=r"(r3) : "r"(addr));
}
__device__ __forceinline__ void ldmat2t(uint32_t& r0, uint32_t& r1, uint32_t addr) {
    asm volatile("ldmatrix.sync.aligned.m8n8.x2.trans.shared.b16 {%0,%1}, [%2];"
                 : "=r"(r0), "=r"(r1) : "r"(addr));
}

// ---------- combined weight convert + transpose (all 6 in one launch) ---------
__global__ void cvt_all(const float* __restrict__ wq, const float* __restrict__ wk,
                        const float* __restrict__ wv, const float* __restrict__ wo,
                        const float* __restrict__ w1, const float* __restrict__ w2) {
    const int BE = (EMB / 32) * (EMB / 32);
    const int BF = (FFD / 32) * (EMB / 32);
    int bid = blockIdx.x;
    const float* W; __half* WT; int K, N, lb;
    if (bid < BE)            { W = wq; WT = g_wqT; K = EMB; N = EMB; lb = bid; }
    else if (bid < 2 * BE)   { W = wk; WT = g_wkT; K = EMB; N = EMB; lb = bid - BE; }
    else if (bid < 3 * BE)   { W = wv; WT = g_wvT; K = EMB; N = EMB; lb = bid - 2 * BE; }
    else if (bid < 4 * BE)   { W = wo; WT = g_woT; K = EMB; N = EMB; lb = bid - 3 * BE; }
    else if (bid < 4 * BE + BF) { W = w1; WT = g_w1T; K = EMB; N = FFD; lb = bid - 4 * BE; }
    else                     { W = w2; WT = g_w2T; K = FFD; N = EMB; lb = bid - 4 * BE - BF; }

    int nb = N / 32;
    int n0 = (lb % nb) * 32, k0 = (lb / nb) * 32;

    __shared__ float tile[32][33];
    int tx = threadIdx.x, ty = threadIdx.y;
#pragma unroll
    for (int j = 0; j < 4; j++)
        tile[ty + j * 8][tx] = W[(size_t)(k0 + ty + j * 8) * N + n0 + tx];
    __syncthreads();
#pragma unroll
    for (int j = 0; j < 4; j++)
        WT[(size_t)(n0 + ty + j * 8) * K + k0 + tx] = __float2half(tile[tx][ty + j * 8]);
}

// ------------------------ LayerNorm (vectorized, fp16 out) --------------------
__global__ void ln_kernel(const float* __restrict__ x, const float* __restrict__ g,
                          const float* __restrict__ b, __half* __restrict__ out) {
    int t = blockIdx.x;
    int tid = threadIdx.x;
    int lane = tid & 31, w = tid >> 5;

    float4 v4 = *(const float4*)(x + (size_t)t * EMB + tid * 4);
    float sum = v4.x + v4.y + v4.z + v4.w;
    float sq  = v4.x * v4.x + v4.y * v4.y + v4.z * v4.z + v4.w * v4.w;
#pragma unroll
    for (int o = 16; o > 0; o >>= 1) {
        sum += __shfl_xor_sync(0xffffffffu, sum, o);
        sq  += __shfl_xor_sync(0xffffffffu, sq, o);
    }
    __shared__ float s1[8], s2[8];
    if (lane == 0) { s1[w] = sum; s2[w] = sq; }
    __syncthreads();
    float tot = 0.f, tq = 0.f;
#pragma unroll
    for (int i = 0; i < 8; i++) { tot += s1[i]; tq += s2[i]; }
    float mu   = tot * (1.f / EMB);
    float rstd = rsqrtf(tq * (1.f / EMB) - mu * mu + 1e-5f);

    float4 g4 = *(const float4*)(g + tid * 4);
    float4 b4 = *(const float4*)(b + tid * 4);
    uint32_t h0 = pack_h2((v4.x - mu) * rstd * g4.x + b4.x,
                          (v4.y - mu) * rstd * g4.y + b4.y);
    uint32_t h1 = pack_h2((v4.z - mu) * rstd * g4.z + b4.z,
                          (v4.w - mu) * rstd * g4.w + b4.w);
    *(uint2*)(out + (size_t)t * EMB + tid * 4) = make_uint2(h0, h1);
}

// ---- fp16 mma GEMM: 512 thr, 16 warps (4x4), 32x32 warp tile, BK=32, NSTG=4 --
#define ABY   (128 * 80)
#define BBY   (128 * 80)
#define NSTG  4
#define GSM   (NSTG * (ABY + BBY))   // 75776 -> 2 CTA/SM

template <int ACT, int OH>
__device__ __forceinline__
void hgemm_core(const __half* __restrict__ A, const __half* __restrict__ WT,
                const float* __restrict__ bias, const float* __restrict__ res,
                void* __restrict__ Cv, int M, int N, int K, int m0, int n0,
                char* smem) {
    uint32_t sbase = smem_u32(smem);
    int tid  = threadIdx.x;
    int lane = tid & 31, warp = tid >> 5;      // warp 0..15
    int g = lane >> 2, t = lane & 3;
    int wm = (warp >> 2) * 32;                 // 0,32,64,96
    int wn = (warp & 3) * 32;                  // 0,32,64,96

    int lm_r = ((lane >> 3) & 1) * 8 + (lane & 7);
    int lm_k = (lane >> 4) * 8;

    // cp.async: 512 threads, 16B each -> 8KB tile per matrix
    int rrow = tid >> 2;                       // 0..127
    int rc   = (tid & 3) * 8;                  // half offset 0,8,16,24

    const __half* Ap = A  + (size_t)(m0 + rrow) * K + rc;
    const __half* Bp = WT + (size_t)(n0 + rrow) * K + rc;
    uint32_t a_dst0 = sbase + rrow * 80 + rc * 2;
    uint32_t b_dst0 = sbase + NSTG * ABY + rrow * 80 + rc * 2;

    int nkb = K >> 5;

#define ISSUEH(kb, s)                                                          \
    do {                                                                       \
        cp_async16(a_dst0 + (s) * ABY, Ap + (size_t)(kb) * 32);                \
        cp_async16(b_dst0 + (s) * BBY, Bp + (size_t)(kb) * 32);                \
    } while (0)

#pragma unroll
    for (int s = 0; s < NSTG - 1; s++) {
        if (s < nkb) ISSUEH(s, s);
        cp_commit();
    }

    float acc[2][4][4] = {};

    for (int kb = 0; kb < nkb; kb++) {
        cp_wait2();
        __syncthreads();

        if (kb + NSTG - 1 < nkb) ISSUEH(kb + NSTG - 1, (kb + NSTG - 1) & (NSTG - 1));
        cp_commit();

        int buf = kb & (NSTG - 1);
        uint32_t abase = sbase + buf * ABY;
        uint32_t bbase = sbase + NSTG * ABY + buf * BBY;

#pragma unroll
        for (int ks = 0; ks < 2; ks++) {
            uint32_t a[2][4], b[4][2];
#pragma unroll
            for (int mf = 0; mf < 2; mf++) {
                uint32_t addr = abase +
                    (uint32_t)((wm + mf * 16 + lm_r) * 80 + (ks * 16 + lm_k) * 2);
                ldmat4(a[mf][0], a[mf][1], a[mf][2], a[mf][3], addr);
            }
#pragma unroll
            for (int pr = 0; pr < 2; pr++) {
                uint32_t r0, r1, r2, r3;
                uint32_t addr = bbase +
                    (uint32_t)((wn + pr * 16 + lm_r) * 80 + (ks * 16 + lm_k) * 2);
                ldmat4(r0, r1, r2, r3, addr);
                b[2 * pr][0] = r0; b[2 * pr + 1][0] = r1;
                b[2 * pr][1] = r2; b[2 * pr + 1][1] = r3;
            }
#pragma unroll
            for (int mf = 0; mf < 2; mf++)
#pragma unroll
                for (int nf = 0; nf < 4; nf++)
                    mma_f16(acc[mf][nf], a[mf], b[nf]);
        }
    }
#undef ISSUEH

#pragma unroll
    for (int mf = 0; mf < 2; mf++) {
#pragma unroll
        for (int nf = 0; nf < 4; nf++) {
            int mA = m0 + wm + mf * 16 + g;
            int mB = mA + 8;
            int n_ = n0 + wn + nf * 8 + 2 * t;
            float bn0 = bias[n_], bn1 = bias[n_ + 1];

            float v00 = acc[mf][nf][0] + bn0;
            float v01 = acc[mf][nf][1] + bn1;
            float v10 = acc[mf][nf][2] + bn0;
            float v11 = acc[mf][nf][3] + bn1;
            if (res) {
                const float2 r0 = *(const float2*)(res + (size_t)mA * N + n_);
                const float2 r1 = *(const float2*)(res + (size_t)mB * N + n_);
                v00 += r0.x; v01 += r0.y; v10 += r1.x; v11 += r1.y;
            }
            if (ACT == 1) {
                v00 = 0.5f * v00 * (1.f + erff(v00 * 0.70710678118654752f));
                v01 = 0.5f * v01 * (1.f + erff(v01 * 0.70710678118654752f));
                v10 = 0.5f * v10 * (1.f + erff(v10 * 0.70710678118654752f));
                v11 = 0.5f * v11 * (1.f + erff(v11 * 0.70710678118654752f));
            }
            if (OH == 1) {
                __half* Ch = (__half*)Cv;
                *(uint32_t*)(Ch + (size_t)mA * N + n_) = pack_h2(v00, v01);
                *(uint32_t*)(Ch + (size_t)mB * N + n_) = pack_h2(v10, v11);
            } else {
                float* Cf = (float*)Cv;
                *(float2*)(Cf + (size_t)mA * N + n_) = make_float2(v00, v01);
                *(float2*)(Cf + (size_t)mB * N + n_) = make_float2(v10, v11);
            }
        }
    }
}

template <int ACT, int OH>
__global__ __launch_bounds__(512, 2)
void h_gemm(const __half* __restrict__ A, const __half* __restrict__ WT,
            const float* __restrict__ bias, const float* __restrict__ res,
            void* __restrict__ C, int M, int N, int K) {
    extern __shared__ char smem[];
    hgemm_core<ACT, OH>(A, WT, bias, res, C, M, N, K,
                        blockIdx.y * 128, blockIdx.x * 128, smem);
}

__global__ __launch_bounds__(512, 2)
void qkv_gemm(const __half* __restrict__ A,
              const float* __restrict__ bq, const float* __restrict__ bk,
              const float* __restrict__ bv,
              __half* __restrict__ Qo, __half* __restrict__ Ko,
              __half* __restrict__ Vo) {
    extern __shared__ char smem[];
    int wsel = blockIdx.x >> 3;
    int n0   = (blockIdx.x & 7) * 128;
    const __half* W;
    const float* bias;
    __half* C;
    if (wsel == 0)      { W = g_wqT; bias = bq; C = Qo; }
    else if (wsel == 1) { W = g_wkT; bias = bk; C = Ko; }
    else                { W = g_wvT; bias = bv; C = Vo; }
    hgemm_core<0, 1>(A, W, bias, nullptr, C, TOK, EMB, EMB,
                     blockIdx.y * 128, n0, smem);
}

// ------ fp16 flash attention (R12 exact: 64-row Q, ex2.f16x2, ones-col) ------
#define HST 72
#define L2E 1.44269504088896340736f

__global__ __launch_bounds__(128)
void attn_h(const __half* __restrict__ Q, const __half* __restrict__ K,
            const __half* __restrict__ V, __half* __restrict__ O) {
    extern __shared__ __half smh[];
    __half* Qs = smh;
    __half* Ks = Qs + 64 * HST;
    __half* Vs = Ks + 64 * HST;
    uint32_t ks_base = smem_u32(Ks);
    uint32_t vs_base = smem_u32(Vs);

    int qt = (int)gridDim.x - 1 - (int)blockIdx.x;
    int bh = blockIdx.y;
    int bb = bh >> 4, hh = bh & 15;
    int tid  = threadIdx.x;
    int warp = tid >> 5, lane = tid & 31;
    int g = lane >> 2, t = lane & 3;
    int r0 = warp * 16;

    size_t base = (size_t)bb * SEQ * EMB + (size_t)hh * HDIM;

    {
        int r = tid >> 1;
        int w = (tid & 1) * 2;
        uint2 val = make_uint2((tid & 1) == 0 ? 0x00003C00u : 0u, 0u);
        *(uint2*)&Vs[r * HST + 64 + w * 2] = val;
    }

    const __half2 sc8 = __float2half2_rn(0.125f);
#pragma unroll
    for (int it = 0; it < 8; it++) {
        int r = (tid >> 4) + it * 8;
        int c = (tid & 15) * 4;
        const __half2* qp = (const __half2*)(Q + base + (size_t)(qt * 64 + r) * EMB + c);
        *(__half2*)&Qs[r * HST + c]     = __hmul2(qp[0], sc8);
        *(__half2*)&Qs[r * HST + c + 2] = __hmul2(qp[1], sc8);
    }
    __syncthreads();

    uint32_t qa[4][4];
#pragma unroll
    for (int kc = 0; kc < 4; kc++) {
        qa[kc][0] = *(const uint32_t*)&Qs[(r0 + g)     * HST + kc * 16 + 2 * t];
        qa[kc][1] = *(const uint32_t*)&Qs[(r0 + g + 8) * HST + kc * 16 + 2 * t];
        qa[kc][2] = *(const uint32_t*)&Qs[(r0 + g)     * HST + kc * 16 + 2 * t + 8];
        qa[kc][3] = *(const uint32_t*)&Qs[(r0 + g + 8) * HST + kc * 16 + 2 * t + 8];
    }

    float o[8][4] = {};
    float oex[4] = {};
    float m0 = -1e30f, m1 = -1e30f;

    int lm_r = ((lane >> 3) & 1) * 8 + (lane & 7);
    int lm_k = (lane >> 4) * 8;

    for (int kt = 0; kt <= qt; kt++) {
#pragma unroll
        for (int it = 0; it < 8; it++) {
            int r = (tid >> 4) + it * 8;
            int c = (tid & 15) * 4;
            size_t go = base + (size_t)(kt * 64 + r) * EMB + c;
            *(uint2*)&Ks[r * HST + c] = *(const uint2*)(K + go);
            *(uint2*)&Vs[r * HST + c] = *(const uint2*)(V + go);
        }
        __syncthreads();

        float s[8][4] = {};
#pragma unroll
        for (int np = 0; np < 4; np++) {
#pragma unroll
            for (int kc = 0; kc < 4; kc++) {
                uint32_t r0v, r1v, r2v, r3v;
                uint32_t addr = ks_base +
                    (uint32_t)(((np * 16 + lm_r) * HST + kc * 16 + lm_k) * 2);
                ldmat4(r0v, r1v, r2v, r3v, addr);
                uint32_t b0[2] = { r0v, r2v };
                uint32_t b1[2] = { r1v, r3v };
                mma_f16(s[2 * np],     qa[kc], b0);
                mma_f16(s[2 * np + 1], qa[kc], b1);
            }
        }

        if (kt == qt) {
            int rowA = r0 + g, rowB = r0 + g + 8;
#pragma unroll
            for (int nf = 0; nf < 8; nf++) {
                int c0 = nf * 8 + 2 * t, c1 = c0 + 1;
                if (c0 > rowA) s[nf][0] = -1e30f;
                if (c1 > rowA) s[nf][1] = -1e30f;
                if (c0 > rowB) s[nf][2] = -1e30f;
                if (c1 > rowB) s[nf][3] = -1e30f;
            }
        }

        float mx0 = -1e30f, mx1 = -1e30f;
#pragma unroll
        for (int nf = 0; nf < 8; nf++) {
            mx0 = fmaxf(mx0, fmaxf(s[nf][0], s[nf][1]));
            mx1 = fmaxf(mx1, fmaxf(s[nf][2], s[nf][3]));
        }
        mx0 = fmaxf(mx0, __shfl_xor_sync(0xffffffffu, mx0, 1));
        mx0 = fmaxf(mx0, __shfl_xor_sync(0xffffffffu, mx0, 2));
        mx1 = fmaxf(mx1, __shfl_xor_sync(0xffffffffu, mx1, 1));
        mx1 = fmaxf(mx1, __shfl_xor_sync(0xffffffffu, mx1, 2));

        float m0n = fmaxf(m0, mx0), m1n = fmaxf(m1, mx1);
        float rs0 = __expf(m0 - m0n), rs1 = __expf(m1 - m1n);
        m0 = m0n; m1 = m1n;
        float mL0 = m0 * L2E, mL1 = m1 * L2E;

        uint32_t pa[4][4];
#pragma unroll
        for (int j = 0; j < 4; j++) {
            pa[j][0] = ex2_h2(pack_h2(fmaf(s[2*j][0],   L2E, -mL0),
                                      fmaf(s[2*j][1],   L2E, -mL0)));
            pa[j][1] = ex2_h2(pack_h2(fmaf(s[2*j][2],   L2E, -mL1),
                                      fmaf(s[2*j][3],   L2E, -mL1)));
            pa[j][2] = ex2_h2(pack_h2(fmaf(s[2*j+1][0], L2E, -mL0),
                                      fmaf(s[2*j+1][1], L2E, -mL0)));
            pa[j][3] = ex2_h2(pack_h2(fmaf(s[2*j+1][2], L2E, -mL1),
                                      fmaf(s[2*j+1][3], L2E, -mL1)));
        }

#pragma unroll
        for (int nf = 0; nf < 8; nf++) {
            o[nf][0] *= rs0; o[nf][1] *= rs0;
            o[nf][2] *= rs1; o[nf][3] *= rs1;
        }
        oex[0] *= rs0; oex[1] *= rs0; oex[2] *= rs1; oex[3] *= rs1;

#pragma unroll
        for (int j = 0; j < 4; j++) {
#pragma unroll
            for (int nfp = 0; nfp < 4; nfp++) {
                uint32_t r0v, r1v, r2v, r3v;
                uint32_t addr = vs_base +
                    (uint32_t)(((j * 16 + lm_r) * HST + nfp * 16 + lm_k) * 2);
                ldmat4t(r0v, r1v, r2v, r3v, addr);
                uint32_t b0[2] = { r0v, r1v };
                uint32_t b1[2] = { r2v, r3v };
                mma_f16(o[2 * nfp],     pa[j], b0);
                mma_f16(o[2 * nfp + 1], pa[j], b1);
            }
            {
                uint32_t e0, e1;
                uint32_t addr = vs_base +
                    (uint32_t)(((j * 16 + (lane & 15)) * HST + 64) * 2);
                ldmat2t(e0, e1, addr);
                uint32_t be[2] = { e0, e1 };
                mma_f16(oex, pa[j], be);
            }
        }
        __syncthreads();
    }

    float lA = __shfl_sync(0xffffffffu, oex[0], lane & ~3);
    float lB = __shfl_sync(0xffffffffu, oex[2], lane & ~3);
    float il0 = 1.f / lA, il1 = 1.f / lB;

    int rowA = qt * 64 + r0 + g;
    int rowB = rowA + 8;
#pragma unroll
    for (int nf = 0; nf < 8; nf++) {
        int c = nf * 8 + 2 * t;
        *(uint32_t*)(O + base + (size_t)rowA * EMB + c) =
            pack_h2(o[nf][0] * il0, o[nf][1] * il0);
        *(uint32_t*)(O + base + (size_t)rowB * EMB + c) =
            pack_h2(o[nf][2] * il1, o[nf][3] * il1);
    }
}

// ------------------------------- launch --------------------------------------
extern "C" void kernel_launch(void* const* d_in, const int* in_sizes, int n_in,
                              void* d_out, int out_size) {
    const float* x     = (const float*)d_in[0];
    const float* ln1_g = (const float*)d_in[2];
    const float* ln1_b = (const float*)d_in[3];
    const float* wq    = (const float*)d_in[4];
    const float* bq    = (const float*)d_in[5];
    const float* wk    = (const float*)d_in[6];
    const float* bk    = (const float*)d_in[7];
    const float* wv    = (const float*)d_in[8];
    const float* bv    = (const float*)d_in[9];
    const float* wo    = (const float*)d_in[10];
    const float* bo    = (const float*)d_in[11];
    const float* ln2_g = (const float*)d_in[12];
    const float* ln2_b = (const float*)d_in[13];
    const float* w1    = (const float*)d_in[14];
    const float* b1    = (const float*)d_in[15];
    const float* w2    = (const float*)d_in[16];
    const float* b2    = (const float*)d_in[17];
    float* out = (float*)d_out;

    __half *h, *q, *k, *v, *at, *h2, *ff;
    float *x1;
    cudaGetSymbolAddress((void**)&h,  g_h);
    cudaGetSymbolAddress((void**)&q,  g_q);
    cudaGetSymbolAddress((void**)&k,  g_k);
    cudaGetSymbolAddress((void**)&v,  g_v);
    cudaGetSymbolAddress((void**)&at, g_at);
    cudaGetSymbolAddress((void**)&x1, g_x1);
    cudaGetSymbolAddress((void**)&h2, g_h2);
    cudaGetSymbolAddress((void**)&ff, g_ff);
    __half *woT, *w1T, *w2T;
    cudaGetSymbolAddress((void**)&woT, g_woT);
    cudaGetSymbolAddress((void**)&w1T, g_w1T);
    cudaGetSymbolAddress((void**)&w2T, g_w2T);

    const int ATTN_SMEM = 3 * 64 * HST * sizeof(__half);   // 27648
    cudaFuncSetAttribute(attn_h, cudaFuncAttributeMaxDynamicSharedMemorySize, ATTN_SMEM);
    cudaFuncSetAttribute(h_gemm<0, 0>, cudaFuncAttributeMaxDynamicSharedMemorySize, GSM);
    cudaFuncSetAttribute(h_gemm<1, 1>, cudaFuncAttributeMaxDynamicSharedMemorySize, GSM);
    cudaFuncSetAttribute(qkv_gemm, cudaFuncAttributeMaxDynamicSharedMemorySize, GSM);

    cvt_all<<<12288, dim3(32, 8)>>>(wq, wk, wv, wo, w1, w2);

    ln_kernel<<<TOK, 256>>>(x, ln1_g, ln1_b, h);

    qkv_gemm<<<dim3(24, TOK / 128), 512, GSM>>>(h, bq, bk, bv, q, k, v);

    attn_h<<<dim3(SEQ / 64, 2 * NHEAD), 128, ATTN_SMEM>>>(q, k, v, at);

    dim3 gE(EMB / 128, TOK / 128);
    h_gemm<0, 0><<<gE, 512, GSM>>>(at, woT, bo, x, x1, TOK, EMB, EMB);

    ln_kernel<<<TOK, 256>>>(x1, ln2_g, ln2_b, h2);

    dim3 gF1(FFD / 128, TOK / 128);
    h_gemm<1, 1><<<gF1, 512, GSM>>>(h2, w1T, b1, nullptr, ff, TOK, FFD, EMB);
    h_gemm<0, 0><<<gE, 512, GSM>>>(ff, w2T, b2, x1, out, TOK, EMB, FFD);
}